// round 9
// baseline (speedup 1.0000x reference)
#include <cuda_runtime.h>
#include <math.h>

// ---------------------------------------------------------------------------
// Static device scratch (allocation-free rule). Zero-initialized at load.
// ---------------------------------------------------------------------------
#define MAX_M 50432
#define LC    256                  // chunk length for linear G/I scans
#define LSEG  3200                 // stored segment length  (multiple of 64)
#define NSEG  16                   // 16*3200 = 51200 >= m-1
#define WARM  9600                 // warmup sync length     (multiple of 64)
#define TOTAL (NSEG * LSEG)
#define CB4N  ((TOTAL + 128) / 2)  // float4 count incl. prefetch pad

__device__ float  d_Sg[MAX_M];
__device__ float  d_Si[MAX_M];
__device__ float  d_Gl[MAX_M];
__device__ float  d_Il[MAX_M];
__device__ float  d_Gfe[256];
__device__ float  d_Ife[256];
__device__ double d_GstD[256];
__device__ double d_IstD[256];
__device__ double d_Ptab[256];
__device__ float4 d_cb4[CB4N];             // float2 view: per-step (c, b)
__device__ float  g_W[NSEG];               // warmup value at segment start
__device__ float  g_E[NSEG];               // exit value at segment end
__device__ int    g_flag[2];               // "all links ok" flags (parity)
__device__ int    g_bar_count;
__device__ int    g_bar_sense;

// ---------------------------------------------------------------------------
// Kernel 1: per-row weighted sums (L2-resident stream).
// ---------------------------------------------------------------------------
__global__ void rowdot_kernel(const float* __restrict__ spikes,
                              const float* __restrict__ w,
                              const float* __restrict__ vrev,
                              int m, int n) {
    __shared__ float4 s_aw[128];
    __shared__ float4 s_wv[128];

    const int tid  = threadIdx.x;
    const int lane = tid & 31;
    const int wrp  = tid >> 5;
    const int nv4  = n >> 2;

    for (int j = tid; j < nv4; j += blockDim.x) {
        float4 wj = reinterpret_cast<const float4*>(w)[j];
        float4 vj = reinterpret_cast<const float4*>(vrev)[j];
        float4 aw = make_float4(fabsf(wj.x), fabsf(wj.y), fabsf(wj.z), fabsf(wj.w));
        s_aw[j] = aw;
        s_wv[j] = make_float4(__fmul_rn(vj.x, aw.x), __fmul_rn(vj.y, aw.y),
                              __fmul_rn(vj.z, aw.z), __fmul_rn(vj.w, aw.w));
    }
    __syncthreads();

    const int row = blockIdx.x * (blockDim.x >> 5) + wrp;
    if (row >= m) return;

    const float4* rp = reinterpret_cast<const float4*>(spikes + (size_t)row * n);
    float accg = 0.0f, acci = 0.0f;
    for (int j = lane; j < nv4; j += 32) {
        float4 s  = rp[j];
        float4 aw = s_aw[j];
        float4 wv = s_wv[j];
        accg = fmaf(s.x, aw.x, accg); accg = fmaf(s.y, aw.y, accg);
        accg = fmaf(s.z, aw.z, accg); accg = fmaf(s.w, aw.w, accg);
        acci = fmaf(s.x, wv.x, acci); acci = fmaf(s.y, wv.y, acci);
        acci = fmaf(s.z, wv.z, acci); acci = fmaf(s.w, wv.w, acci);
    }
    for (int j = (nv4 << 2) + lane; j < n; j += 32) {
        float aw = fabsf(w[j]);
        float sv = spikes[(size_t)row * n + j];
        accg = fmaf(sv, aw, accg);
        acci = fmaf(sv, __fmul_rn(vrev[j], aw), acci);
    }

    #pragma unroll
    for (int o = 16; o > 0; o >>= 1) {
        accg += __shfl_down_sync(0xffffffffu, accg, o);
        acci += __shfl_down_sync(0xffffffffu, acci, o);
    }
    if (lane == 0) {
        d_Sg[row] = accg;
        d_Si[row] = acci;
    }
}

// ---------------------------------------------------------------------------
// Kernel 2: chunk-local forced responses (exact ref op order within chunk).
// ---------------------------------------------------------------------------
__global__ void chains_kernel(int nchunk) {
    const int c    = blockIdx.x;
    const int lane = threadIdx.x;
    const int base = c * LC;
    const float d  = expf(-0.1f);

    float sg[8], si[8];
    #pragma unroll
    for (int q = 0; q < 8; ++q) {
        sg[q] = d_Sg[base + q * 32 + lane];
        si[q] = d_Si[base + q * 32 + lane];
    }

    float G = 0.0f, I = 0.0f;
    #pragma unroll
    for (int q = 0; q < 8; ++q) {
        float gs = 0.0f, is = 0.0f;
        #pragma unroll
        for (int k = 0; k < 32; ++k) {
            const float sgk = __shfl_sync(0xffffffffu, sg[q], k);
            const float sik = __shfl_sync(0xffffffffu, si[q], k);
            if (k == lane) { gs = G; is = I; }
            G = __fmul_rn(__fadd_rn(G, sgk), d);
            I = __fmul_rn(__fadd_rn(I, sik), d);
        }
        d_Gl[base + q * 32 + lane] = gs;
        d_Il[base + q * 32 + lane] = is;
    }
    if (lane == 0) { d_Gfe[c] = G; d_Ife[c] = I; }
}

// ---------------------------------------------------------------------------
// Kernel 3: chunk carries via affine warp-scan in double + P table.
// ---------------------------------------------------------------------------
__global__ void carry_kernel(int nchunk) {     // 1 block x 64 threads
    const int tid = threadIdx.x;
    const double lg = log((double)expf(-0.1f));

    for (int j = tid; j < 256; j += 64) d_Ptab[j] = exp((double)j * lg);
    if (tid >= 32) return;

    const int    lane = tid;
    const double D    = exp((double)LC * lg);
    const int    per  = 7;
    const int    c0   = lane * per;

    double A = 1.0, Bg = 0.0, Bi = 0.0;
    for (int q = 0; q < per; ++q) {
        const int c = c0 + q;
        const double feg = (c < nchunk) ? (double)d_Gfe[c] : 0.0;
        const double fei = (c < nchunk) ? (double)d_Ife[c] : 0.0;
        A  = A * D;
        Bg = Bg * D + feg;
        Bi = Bi * D + fei;
    }
    double Ai = A, BgI = Bg, BiI = Bi;
    for (int o = 1; o < 32; o <<= 1) {
        const double A1  = __shfl_up_sync(0xffffffffu, Ai, o);
        const double Bg1 = __shfl_up_sync(0xffffffffu, BgI, o);
        const double Bi1 = __shfl_up_sync(0xffffffffu, BiI, o);
        if (lane >= o) {
            BgI = Bg1 * Ai + BgI;
            BiI = Bi1 * Ai + BiI;
            Ai  = A1 * Ai;
        }
    }
    const double hgp = __shfl_up_sync(0xffffffffu, BgI, 1);
    const double hip = __shfl_up_sync(0xffffffffu, BiI, 1);
    double Hg = (lane > 0) ? hgp : 0.0;
    double Hi = (lane > 0) ? hip : 0.0;
    for (int q = 0; q < per; ++q) {
        const int c = c0 + q;
        if (c < nchunk) {
            d_GstD[c] = Hg; d_IstD[c] = Hi;
            Hg = Hg * D + (double)d_Gfe[c];
            Hi = Hi * D + (double)d_Ife[c];
        }
    }
}

// ---------------------------------------------------------------------------
// Kernel 4: recombine + emit (c,b); reset solver state. Pad = identity step.
// ---------------------------------------------------------------------------
__global__ void combine_kernel(float* __restrict__ vtr, int m) {
    const int i = blockIdx.x * blockDim.x + threadIdx.x;
    if (i >= TOTAL) return;
    float2* cb = reinterpret_cast<float2*>(d_cb4);

    if (i == 0) {
        g_flag[0] = 1; g_flag[1] = 1;
        g_bar_count = 0; g_bar_sense = 0;
        vtr[0] = 0.0f;
    }

    if (i >= m - 1) { cb[i] = make_float2(1.0f, 0.0f); return; }

    const int c   = i >> 8;
    const int off = i & 255;
    const double P = d_Ptab[off];

    const float G = (float)((double)d_Gl[i] + d_GstD[c] * P);
    const float I = (float)((double)d_Il[i] + d_IstD[c] * P);

    const float a  = __fmul_rn(0.001f, __fadd_rn(1.0f, G));
    const float cf = __fadd_rn(1.0f, -a);
    const float b  = __fmul_rn(0.001f, I);
    cb[i] = make_float2(cf, b);
}

// ---------------------------------------------------------------------------
// Kernel 5: self-synchronizing overlapped segments + certificate check.
//
// Pass 1 (parallel): block k starts from v=0 at index max(0, k*LSEG-WARM),
// runs the BIT-EXACT step map (mul.rn -> add.rn, setp||selp) through WARM
// warmup steps (reset-synchronization) then stores its LSEG segment.
// Records W_k = v at segment start, E_k = v at segment end.
//
// Certificate: bits(W_k) == bits(E_{k-1}) for all k, chained from block 0's
// anchored v=0 start, PROVES the stored output is the exact sequential
// trajectory. Failed links repair via bounded wavefront re-runs (with
// bitwise merge-detection against the stored trajectory), <= NSEG rounds.
// ---------------------------------------------------------------------------
#define ESTEP(cc, bb) do {                                        \
    float _vn;                                                    \
    asm("{\n\t"                                                   \
        ".reg .pred p;\n\t"                                       \
        ".reg .f32 t;\n\t"                                        \
        "mul.rn.f32 t, %1, %2;\n\t"                               \
        "add.rn.f32 t, t, %3;\n\t"                                \
        "setp.lt.f32 p, %1, 0f3F800000;\n\t"                      \
        "selp.f32 %0, t, 0f00000000, p;\n\t"                      \
        "}" : "=f"(_vn) : "f"(v), "f"(cc), "f"(bb));              \
    v = _vn;                                                      \
} while (0)

__device__ __forceinline__ void grid_barrier(int lane, int &sense, int arm) {
    if (lane == 0) {
        const int s = sense ^ 1;
        __threadfence();
        if (atomicAdd(&g_bar_count, 1) == NSEG - 1) {
            g_bar_count = 0;
            if (arm >= 0) g_flag[arm] = 1;
            __threadfence();
            g_bar_sense = s;
        } else {
            while (*((volatile int*)&g_bar_sense) != s) { }
        }
        __threadfence();
    }
    sense ^= 1;
    __syncwarp();
}

// Run nsteps (multiple of 64, may be 0) of the exact map from *pv, starting
// at global step index `start`. STORE: write outputs to vtr. CHECK: compare
// against stored trajectory, stop at first bitwise match (returns 1).
template<bool STORE, bool CHECK>
__device__ __forceinline__ int run_steps(int start, int nsteps, float& vref,
                                         float* __restrict__ vtr, int m,
                                         int lane) {
    float v = vref;
    const float4* cbp = d_cb4 + (start >> 1);
    const int nb = nsteps >> 6;            // 64-step blocks
    int merged = 0;

    float4 A[16], B[16];
    #pragma unroll
    for (int j = 0; j < 16; ++j) A[j] = cbp[j];

    for (int t = 0; t < nb; ++t) {
        if (merged) break;
        const float4* pB = cbp + (t * 2 + 1) * 16;
        #pragma unroll
        for (int j = 0; j < 16; ++j) B[j] = pB[j];
        // ---- 32 steps on A ----
        {
            const int  i  = start + t * 64 + 1 + lane;
            float spec = 0.0f, vout = 0.0f;
            if (CHECK && i < m) spec = vtr[i];
            #pragma unroll
            for (int j = 0; j < 16; ++j) {
                ESTEP(A[j].x, A[j].y);
                if (STORE || CHECK) vout = (2 * j == lane) ? v : vout;
                ESTEP(A[j].z, A[j].w);
                if (STORE || CHECK) vout = (2 * j + 1 == lane) ? v : vout;
            }
            if (CHECK) {
                const unsigned eq = __ballot_sync(0xffffffffu, (i < m) &&
                    (__float_as_uint(vout) == __float_as_uint(spec)));
                if (STORE && i < m) vtr[i] = vout;
                if (eq) merged = 1;
            } else if (STORE && i < m) vtr[i] = vout;
        }
        const float4* pA = cbp + (t * 2 + 2) * 16;
        #pragma unroll
        for (int j = 0; j < 16; ++j) A[j] = pA[j];
        // ---- 32 steps on B ----
        if (!merged) {
            const int  i  = start + t * 64 + 32 + 1 + lane;
            float spec = 0.0f, vout = 0.0f;
            if (CHECK && i < m) spec = vtr[i];
            #pragma unroll
            for (int j = 0; j < 16; ++j) {
                ESTEP(B[j].x, B[j].y);
                if (STORE || CHECK) vout = (2 * j == lane) ? v : vout;
                ESTEP(B[j].z, B[j].w);
                if (STORE || CHECK) vout = (2 * j + 1 == lane) ? v : vout;
            }
            if (CHECK) {
                const unsigned eq = __ballot_sync(0xffffffffu, (i < m) &&
                    (__float_as_uint(vout) == __float_as_uint(spec)));
                if (STORE && i < m) vtr[i] = vout;
                if (eq) merged = 1;
            } else if (STORE && i < m) vtr[i] = vout;
        }
    }
    vref = v;
    return merged;
}

__global__ void __launch_bounds__(32, 1) solve_kernel(float* __restrict__ vtr,
                                                      int m) {
    const int k       = blockIdx.x;
    const int lane    = threadIdx.x;
    const int segbase = k * LSEG;
    int start = segbase - WARM;
    if (start < 0) start = 0;
    int sense = 0;

    // ---- Pass 1: warmup (sync) + stored segment ----
    float v = 0.0f;
    run_steps<false, false>(start, segbase - start, v, vtr, m, lane);
    if (lane == 0) g_W[k] = v;
    run_steps<true, false>(segbase, LSEG, v, vtr, m, lane);
    if (lane == 0) g_E[k] = v;

    grid_barrier(lane, sense, 0);          // publish + arm slot 0

    // ---- Certificate check / bounded repair ----
    for (int r = 0; r < NSEG; ++r) {
        const float Wk = ((volatile float*)g_W)[k];
        const float Ep = (k > 0) ? ((volatile float*)g_E)[k - 1] : 0.0f;
        const bool  bad = (k > 0) &&
            (__float_as_uint(Wk) != __float_as_uint(Ep));
        if (bad && lane == 0) atomicExch(&g_flag[r & 1], 0);
        grid_barrier(lane, sense, (r + 1) & 1);

        int fl = 0;
        if (lane == 0) fl = *((volatile int*)&g_flag[r & 1]);
        fl = __shfl_sync(0xffffffffu, fl, 0);
        if (fl) break;                     // all links verified -> exact

        if (bad) {                         // repair from verified-ish entry
            float vr = Ep;
            const int merged = run_steps<true, true>(segbase, LSEG, vr, vtr, m, lane);
            if (lane == 0) {
                g_W[k] = Ep;               // link k now consistent w/ snapshot
                if (!merged) g_E[k] = vr;  // merged => stored exit unchanged
            }
        }
        grid_barrier(lane, sense, -1);
    }
}

// ---------------------------------------------------------------------------
extern "C" void kernel_launch(void* const* d_in, const int* in_sizes, int n_in,
                              void* d_out, int out_size) {
    const float* spikes = (const float*)d_in[0];
    const float* w      = (const float*)d_in[1];
    const float* vrev   = (const float*)d_in[2];
    float*       vtr    = (float*)d_out;

    const int n = in_sizes[1];                       // 500
    const int m = in_sizes[0] / n;                   // 50000
    const int nchunk = (m + LC - 1) / LC;            // 196

    rowdot_kernel<<<(m + 7) / 8, 256>>>(spikes, w, vrev, m, n);
    chains_kernel<<<nchunk, 32>>>(nchunk);
    carry_kernel<<<1, 64>>>(nchunk);
    combine_kernel<<<(TOTAL + 255) / 256, 256>>>(vtr, m);
    solve_kernel<<<NSEG, 32>>>(vtr, m);
}

// round 10
// speedup vs baseline: 2.3509x; 2.3509x over previous
#include <cuda_runtime.h>
#include <math.h>

// ---------------------------------------------------------------------------
// Static device scratch (allocation-free rule). Zero-initialized at load.
// ---------------------------------------------------------------------------
#define MAX_M  50432
#define LC     256                 // chunk length for linear G/I scans
#define CHUNK  512                 // serial-pipeline chunk (steps)
#define NRING  4                   // smem ring depth (chunks)
#define TOTAL  50176               // 98*512 = 196*256, >= m-1, identity-padded

__device__ float  d_Sg[MAX_M];
__device__ float  d_Si[MAX_M];
__device__ float  d_Gl[MAX_M];
__device__ float  d_Il[MAX_M];
__device__ float  d_Gfe[256];
__device__ float  d_Ife[256];
__device__ double d_GstD[256];
__device__ double d_IstD[256];
__device__ double d_Ptab[256];
__device__ float4 d_cb4[TOTAL / 2];        // float2 view: per-step (c, b)

// ---------------------------------------------------------------------------
// Kernel 1: per-row weighted sums (L2-resident stream).
// ---------------------------------------------------------------------------
__global__ void rowdot_kernel(const float* __restrict__ spikes,
                              const float* __restrict__ w,
                              const float* __restrict__ vrev,
                              int m, int n) {
    __shared__ float4 s_aw[128];
    __shared__ float4 s_wv[128];

    const int tid  = threadIdx.x;
    const int lane = tid & 31;
    const int wrp  = tid >> 5;
    const int nv4  = n >> 2;

    for (int j = tid; j < nv4; j += blockDim.x) {
        float4 wj = reinterpret_cast<const float4*>(w)[j];
        float4 vj = reinterpret_cast<const float4*>(vrev)[j];
        float4 aw = make_float4(fabsf(wj.x), fabsf(wj.y), fabsf(wj.z), fabsf(wj.w));
        s_aw[j] = aw;
        s_wv[j] = make_float4(__fmul_rn(vj.x, aw.x), __fmul_rn(vj.y, aw.y),
                              __fmul_rn(vj.z, aw.z), __fmul_rn(vj.w, aw.w));
    }
    __syncthreads();

    const int row = blockIdx.x * (blockDim.x >> 5) + wrp;
    if (row >= m) return;

    const float4* rp = reinterpret_cast<const float4*>(spikes + (size_t)row * n);
    float accg = 0.0f, acci = 0.0f;
    for (int j = lane; j < nv4; j += 32) {
        float4 s  = rp[j];
        float4 aw = s_aw[j];
        float4 wv = s_wv[j];
        accg = fmaf(s.x, aw.x, accg); accg = fmaf(s.y, aw.y, accg);
        accg = fmaf(s.z, aw.z, accg); accg = fmaf(s.w, aw.w, accg);
        acci = fmaf(s.x, wv.x, acci); acci = fmaf(s.y, wv.y, acci);
        acci = fmaf(s.z, wv.z, acci); acci = fmaf(s.w, wv.w, acci);
    }
    for (int j = (nv4 << 2) + lane; j < n; j += 32) {
        float aw = fabsf(w[j]);
        float sv = spikes[(size_t)row * n + j];
        accg = fmaf(sv, aw, accg);
        acci = fmaf(sv, __fmul_rn(vrev[j], aw), acci);
    }

    #pragma unroll
    for (int o = 16; o > 0; o >>= 1) {
        accg += __shfl_down_sync(0xffffffffu, accg, o);
        acci += __shfl_down_sync(0xffffffffu, acci, o);
    }
    if (lane == 0) {
        d_Sg[row] = accg;
        d_Si[row] = acci;
    }
}

// ---------------------------------------------------------------------------
// Kernel 2: chunk-local forced responses (exact ref op order within chunk).
// ---------------------------------------------------------------------------
__global__ void chains_kernel(int nchunk) {
    const int c    = blockIdx.x;
    const int lane = threadIdx.x;
    const int base = c * LC;
    const float d  = expf(-0.1f);

    float sg[8], si[8];
    #pragma unroll
    for (int q = 0; q < 8; ++q) {
        sg[q] = d_Sg[base + q * 32 + lane];
        si[q] = d_Si[base + q * 32 + lane];
    }

    float G = 0.0f, I = 0.0f;
    #pragma unroll
    for (int q = 0; q < 8; ++q) {
        float gs = 0.0f, is = 0.0f;
        #pragma unroll
        for (int k = 0; k < 32; ++k) {
            const float sgk = __shfl_sync(0xffffffffu, sg[q], k);
            const float sik = __shfl_sync(0xffffffffu, si[q], k);
            if (k == lane) { gs = G; is = I; }
            G = __fmul_rn(__fadd_rn(G, sgk), d);
            I = __fmul_rn(__fadd_rn(I, sik), d);
        }
        d_Gl[base + q * 32 + lane] = gs;
        d_Il[base + q * 32 + lane] = is;
    }
    if (lane == 0) { d_Gfe[c] = G; d_Ife[c] = I; }
}

// ---------------------------------------------------------------------------
// Kernel 3: chunk carries via affine warp-scan in double + P table.
// ---------------------------------------------------------------------------
__global__ void carry_kernel(int nchunk) {     // 1 block x 64 threads
    const int tid = threadIdx.x;
    const double lg = log((double)expf(-0.1f));

    for (int j = tid; j < 256; j += 64) d_Ptab[j] = exp((double)j * lg);
    if (tid >= 32) return;

    const int    lane = tid;
    const double D    = exp((double)LC * lg);
    const int    per  = 7;
    const int    c0   = lane * per;

    double A = 1.0, Bg = 0.0, Bi = 0.0;
    for (int q = 0; q < per; ++q) {
        const int c = c0 + q;
        const double feg = (c < nchunk) ? (double)d_Gfe[c] : 0.0;
        const double fei = (c < nchunk) ? (double)d_Ife[c] : 0.0;
        A  = A * D;
        Bg = Bg * D + feg;
        Bi = Bi * D + fei;
    }
    double Ai = A, BgI = Bg, BiI = Bi;
    for (int o = 1; o < 32; o <<= 1) {
        const double A1  = __shfl_up_sync(0xffffffffu, Ai, o);
        const double Bg1 = __shfl_up_sync(0xffffffffu, BgI, o);
        const double Bi1 = __shfl_up_sync(0xffffffffu, BiI, o);
        if (lane >= o) {
            BgI = Bg1 * Ai + BgI;
            BiI = Bi1 * Ai + BiI;
            Ai  = A1 * Ai;
        }
    }
    const double hgp = __shfl_up_sync(0xffffffffu, BgI, 1);
    const double hip = __shfl_up_sync(0xffffffffu, BiI, 1);
    double Hg = (lane > 0) ? hgp : 0.0;
    double Hi = (lane > 0) ? hip : 0.0;
    for (int q = 0; q < per; ++q) {
        const int c = c0 + q;
        if (c < nchunk) {
            d_GstD[c] = Hg; d_IstD[c] = Hi;
            Hg = Hg * D + (double)d_Gfe[c];
            Hi = Hi * D + (double)d_Ife[c];
        }
    }
}

// ---------------------------------------------------------------------------
// Kernel 4: recombine + emit per-step (c,b). Pad = identity step (c=1,b=0).
// ---------------------------------------------------------------------------
__global__ void combine_kernel(float* __restrict__ vtr, int m) {
    const int i = blockIdx.x * blockDim.x + threadIdx.x;
    if (i >= TOTAL) return;
    float2* cb = reinterpret_cast<float2*>(d_cb4);

    if (i == 0) vtr[0] = 0.0f;
    if (i >= m - 1) { cb[i] = make_float2(1.0f, 0.0f); return; }

    const int c   = i >> 8;
    const int off = i & 255;
    const double P = d_Ptab[off];

    const float G = (float)((double)d_Gl[i] + d_GstD[c] * P);
    const float I = (float)((double)d_Il[i] + d_IstD[c] * P);

    const float a  = __fmul_rn(0.001f, __fadd_rn(1.0f, G));
    const float cf = __fadd_rn(1.0f, -a);
    const float b  = __fmul_rn(0.001f, I);
    cb[i] = make_float2(cf, b);
}

// ---------------------------------------------------------------------------
// Kernel 5: serial executor at the 8-cycle dependency floor.
//
// warp0: runs the UNRESET stream U' = rn(rn(U*c)+b) — bit-identical to the
//        reference step whenever no reset fires. A parallel FMNMX side-chain
//        tracks the window max; if any predecessor in a 32-step window could
//        have been >= 1 (~38 of 1563 windows), a rare uniform branch replays
//        the window with full select semantics (mul.rn -> add.rn -> select =
//        the proven-exact path) from the saved entry. Repaired windows ending
//        >= 1 re-trigger in the next window, so chained resets are handled.
// warp1: streams (c,b) global->smem ring, 3 chunks ahead.
// warp2: drains smem v ring -> vtr, 1 chunk behind.
// One __syncthreads per 512-step chunk.
// ---------------------------------------------------------------------------
__global__ void __launch_bounds__(96, 1) serial_kernel(float* __restrict__ vtr,
                                                       int m, int nchunks) {
    __shared__ float4 s_cb[NRING * CHUNK / 2];   // (c,b) pairs, 2 steps/float4
    __shared__ float  s_v [NRING * CHUNK];

    const int wid  = threadIdx.x >> 5;
    const int lane = threadIdx.x & 31;

    if (threadIdx.x == 0) vtr[0] = 0.0f;

    // prefill cb chunks 0..2
    if (wid == 1) {
        for (int c = 0; c < 3 && c < nchunks; ++c) {
            const float4* src = d_cb4 + c * (CHUNK / 2);
            #pragma unroll
            for (int j = 0; j < CHUNK / 2 / 32; ++j)
                s_cb[c * (CHUNK / 2) + j * 32 + lane] = src[j * 32 + lane];
        }
    }
    __syncthreads();

    float U = 0.0f;

    for (int t = 0; t < nchunks; ++t) {
        if (wid == 0) {
            const int sbase = (t & (NRING - 1)) * CHUNK;
            for (int sb = 0; sb < CHUNK / 32; ++sb) {
                // stage 32 steps of (c,b): 16 float4 (broadcast LDS)
                float4 q[16];
                #pragma unroll
                for (int j = 0; j < 16; ++j)
                    q[j] = s_cb[(sbase + sb * 32) / 2 + j];

                const float entry = U;
                float vmax = U;
                // ---- clean path: pure 8-cycle mul->add chain ----
                #pragma unroll
                for (int j = 0; j < 16; ++j) {
                    U = __fadd_rn(__fmul_rn(U, q[j].x), q[j].y);
                    vmax = fmaxf(vmax, U);
                    s_v[sbase + sb * 32 + 2 * j] = U;
                    U = __fadd_rn(__fmul_rn(U, q[j].z), q[j].w);
                    vmax = fmaxf(vmax, U);
                    s_v[sbase + sb * 32 + 2 * j + 1] = U;
                }
                // ---- rare repair: exact select semantics ----
                if (vmax >= 1.0f) {
                    float v = entry;
                    #pragma unroll 4
                    for (int k = 0; k < 32; ++k) {
                        const float cc = (k & 1) ? q[k >> 1].z : q[k >> 1].x;
                        const float bb = (k & 1) ? q[k >> 1].w : q[k >> 1].y;
                        const float u = __fadd_rn(__fmul_rn(v, cc), bb);
                        v = (v < 1.0f) ? u : 0.0f;
                        s_v[sbase + sb * 32 + k] = v;
                    }
                    U = v;
                }
            }
        } else if (wid == 1) {
            const int f = t + 3;
            if (f < nchunks) {
                const int dst = (f & (NRING - 1)) * (CHUNK / 2);
                const float4* src = d_cb4 + f * (CHUNK / 2);
                #pragma unroll
                for (int j = 0; j < CHUNK / 2 / 32; ++j)
                    s_cb[dst + j * 32 + lane] = src[j * 32 + lane];
            }
        } else if (wid == 2) {
            if (t >= 1) {
                const int d   = t - 1;
                const int src = (d & (NRING - 1)) * CHUNK;
                #pragma unroll
                for (int j = 0; j < CHUNK / 32; ++j) {
                    const int i = d * CHUNK + j * 32 + lane + 1;
                    if (i < m) vtr[i] = s_v[src + j * 32 + lane];
                }
            }
        }
        __syncthreads();
    }
    // drain the final chunk
    if (wid == 2) {
        const int d   = nchunks - 1;
        const int src = (d & (NRING - 1)) * CHUNK;
        #pragma unroll
        for (int j = 0; j < CHUNK / 32; ++j) {
            const int i = d * CHUNK + j * 32 + lane + 1;
            if (i < m) vtr[i] = s_v[src + j * 32 + lane];
        }
    }
}

// ---------------------------------------------------------------------------
extern "C" void kernel_launch(void* const* d_in, const int* in_sizes, int n_in,
                              void* d_out, int out_size) {
    const float* spikes = (const float*)d_in[0];
    const float* w      = (const float*)d_in[1];
    const float* vrev   = (const float*)d_in[2];
    float*       vtr    = (float*)d_out;

    const int n = in_sizes[1];                       // 500
    const int m = in_sizes[0] / n;                   // 50000
    const int nchunk  = (m + LC - 1) / LC;           // 196
    const int nchunks = TOTAL / CHUNK;               // 98

    rowdot_kernel<<<(m + 7) / 8, 256>>>(spikes, w, vrev, m, n);
    chains_kernel<<<nchunk, 32>>>(nchunk);
    carry_kernel<<<1, 64>>>(nchunk);
    combine_kernel<<<(TOTAL + 255) / 256, 256>>>(vtr, m);
    serial_kernel<<<1, 96>>>(vtr, m, nchunks);
}